// round 4
// baseline (speedup 1.0000x reference)
#include <cuda_runtime.h>
#include <mma.h>
#include <cstdint>
#include <math.h>

using namespace nvcuda;

#define BATCH 2
#define SEQ   2048
#define EMB   1024
#define NHEAD 16
#define HDIM  64
#define E3    3072

// Scratch (__device__ globals per allocation rules)
__device__ float g_qkv  [(size_t)BATCH * SEQ * E3];            // 50 MB
__device__ float g_ctx  [(size_t)BATCH * SEQ * EMB];           // 16 MB
__device__ float g_stats[(size_t)BATCH * NHEAD * SEQ * 2];     // 512 KB (m, s per row)
__device__ float g_attn [(size_t)BATCH * NHEAD * SEQ * SEQ];   // 512 MB fallback

typedef wmma::fragment<wmma::matrix_a, 16, 16, 8, wmma::precision::tf32, wmma::row_major> FragA;
typedef wmma::fragment<wmma::matrix_b, 16, 16, 8, wmma::precision::tf32, wmma::row_major> FragBR;
typedef wmma::fragment<wmma::matrix_b, 16, 16, 8, wmma::precision::tf32, wmma::col_major> FragBC;
typedef wmma::fragment<wmma::accumulator, 16, 16, 8, float> FragC;

template<class F>
__device__ __forceinline__ void to_tf32(F& f) {
    #pragma unroll
    for (int i = 0; i < f.num_elements; i++) f.x[i] = wmma::__float_to_tf32(f.x[i]);
}

__device__ __forceinline__ void cpa16(float* s, const float* g) {
    uint32_t sa = (uint32_t)__cvta_generic_to_shared(s);
    asm volatile("cp.async.ca.shared.global [%0], [%1], 16;" :: "r"(sa), "l"(g));
}
#define CP_COMMIT() asm volatile("cp.async.commit_group;" ::: "memory")
#define CP_WAIT(n)  asm volatile("cp.async.wait_group %0;" :: "n"(n) : "memory")

// ---------------------------------------------------------------------------
// GEMM + bias: C[M,N] = A[M,K] @ B[K,N] + bias[N]  (unchanged from R3)
// ---------------------------------------------------------------------------
#define GSM (128 * 132 * 4)

__global__ __launch_bounds__(256) void gemm_bias_w(
    const float* __restrict__ A, const float* __restrict__ B,
    const float* __restrict__ bias, float* __restrict__ C, int K, int N)
{
    extern __shared__ float sm[];
    float* As = sm;                 // [128][36]
    float* Bs = sm + 128 * 36;      // [32][132]
    float* Cs = sm;                 // [128][132] (reused)

    const int m0 = blockIdx.y * 128, n0 = blockIdx.x * 128;
    const int tid = threadIdx.x;
    const int w = tid >> 5;
    const int wr = w >> 1, wc = w & 1;

    FragC acc[2][4];
    #pragma unroll
    for (int i = 0; i < 2; i++)
        #pragma unroll
        for (int j = 0; j < 4; j++) wmma::fill_fragment(acc[i][j], 0.f);

    for (int k0 = 0; k0 < K; k0 += 32) {
        #pragma unroll
        for (int t = 0; t < 4; t++) {
            int idx = tid + t * 256;
            int r = idx >> 3, c = (idx & 7) * 4;
            *(float4*)&As[r * 36 + c] = *(const float4*)&A[(size_t)(m0 + r) * K + k0 + c];
        }
        #pragma unroll
        for (int t = 0; t < 4; t++) {
            int idx = tid + t * 256;
            int r = idx >> 5, c = (idx & 31) * 4;
            *(float4*)&Bs[r * 132 + c] = *(const float4*)&B[(size_t)(k0 + r) * N + n0 + c];
        }
        __syncthreads();

        #pragma unroll
        for (int kk = 0; kk < 32; kk += 8) {
            FragA a[2];
            FragBR b[4];
            #pragma unroll
            for (int i = 0; i < 2; i++) {
                wmma::load_matrix_sync(a[i], &As[(wr * 32 + i * 16) * 36 + kk], 36);
                to_tf32(a[i]);
            }
            #pragma unroll
            for (int j = 0; j < 4; j++) {
                wmma::load_matrix_sync(b[j], &Bs[kk * 132 + wc * 64 + j * 16], 132);
                to_tf32(b[j]);
            }
            #pragma unroll
            for (int i = 0; i < 2; i++)
                #pragma unroll
                for (int j = 0; j < 4; j++)
                    wmma::mma_sync(acc[i][j], a[i], b[j], acc[i][j]);
        }
        __syncthreads();
    }

    #pragma unroll
    for (int i = 0; i < 2; i++)
        #pragma unroll
        for (int j = 0; j < 4; j++)
            wmma::store_matrix_sync(&Cs[(wr * 32 + i * 16) * 132 + wc * 64 + j * 16],
                                    acc[i][j], 132, wmma::mem_row_major);
    __syncthreads();
    #pragma unroll
    for (int t = 0; t < 16; t++) {
        int idx = tid + t * 256;
        int r = idx >> 5, c = (idx & 31) * 4;
        float4 v = *(float4*)&Cs[r * 132 + c];
        const float* bp = bias + n0 + c;
        v.x += bp[0]; v.y += bp[1]; v.z += bp[2]; v.w += bp[3];
        *(float4*)&C[(size_t)(m0 + r) * N + n0 + c] = v;
    }
}

// ---------------------------------------------------------------------------
// Kernel A: fused scores + ALiBi + online softmax stats.
// Block = (i-tile of 128 rows, bh). Loops 32 j-tiles of 64.
// Writes biased scores to attn; final per-row (max, sumexp) to stats.
// ---------------------------------------------------------------------------
#define ASM_A ((128*68 + 2*64*68 + 128*68 + 256) * 4)   // 105472 B

__global__ __launch_bounds__(256) void scores_stats_w(
    const float* __restrict__ qkv, float* __restrict__ attn,
    float* __restrict__ stats)
{
    extern __shared__ float sm[];
    float* Qs   = sm;                         // [128][68]
    float* Ks   = sm + 128 * 68;              // 2 x [64][68]
    float* Ss   = sm + 128 * 68 + 2 * 64 * 68; // [128][68]
    float* Ms   = Ss + 128 * 68;              // [128]
    float* Sums = Ms + 128;                   // [128]

    const int bh = blockIdx.y, b = bh >> 4, h = bh & 15;
    const int i0 = blockIdx.x * 128;
    const float* Qg = qkv + (size_t)b * SEQ * E3 + h * 192;
    const float* Kg = qkv + (size_t)b * SEQ * E3 + h * 192 + 64;
    const int tid = threadIdx.x;
    const int w = tid >> 5, wr = w >> 1, wc = w & 1;
    const float slope = exp2f(-0.5f * (float)(h + 1));

    // Load Q tile 128x64
    #pragma unroll
    for (int t = 0; t < 8; t++) {
        int idx = tid + t * 256;
        int r = idx >> 4, c = (idx & 15) * 4;
        *(float4*)&Qs[r * 68 + c] = *(const float4*)&Qg[(size_t)(i0 + r) * E3 + c];
    }
    if (tid < 128) { Ms[tid] = -INFINITY; Sums[tid] = 0.f; }

    // Prefetch K tile 0
    #pragma unroll
    for (int t = 0; t < 4; t++) {
        int idx = tid + t * 256;
        int r = idx >> 4, c = (idx & 15) * 4;
        cpa16(&Ks[r * 68 + c], &Kg[(size_t)r * E3 + c]);
    }
    CP_COMMIT();

    for (int jt = 0; jt < 32; jt++) {
        __syncthreads();   // prev iter's mma/stats done before buffer reuse
        if (jt + 1 < 32) {
            float* kb = Ks + ((jt + 1) & 1) * 64 * 68;
            const float* kg = Kg + (size_t)(jt + 1) * 64 * E3;
            #pragma unroll
            for (int t = 0; t < 4; t++) {
                int idx = tid + t * 256;
                int r = idx >> 4, c = (idx & 15) * 4;
                cpa16(&kb[r * 68 + c], &kg[(size_t)r * E3 + c]);
            }
            CP_COMMIT();
            CP_WAIT(1);
        } else {
            CP_WAIT(0);
        }
        __syncthreads();

        const float* kbuf = Ks + (jt & 1) * 64 * 68;
        FragC acc[2][2];
        #pragma unroll
        for (int i = 0; i < 2; i++)
            #pragma unroll
            for (int j = 0; j < 2; j++) wmma::fill_fragment(acc[i][j], 0.f);

        #pragma unroll
        for (int kk = 0; kk < 64; kk += 8) {
            FragA a[2];
            FragBC bf[2];
            #pragma unroll
            for (int i = 0; i < 2; i++) {
                wmma::load_matrix_sync(a[i], &Qs[(wr * 32 + i * 16) * 68 + kk], 68);
                to_tf32(a[i]);
            }
            #pragma unroll
            for (int j = 0; j < 2; j++) {
                wmma::load_matrix_sync(bf[j], &kbuf[(wc * 32 + j * 16) * 68 + kk], 68);
                to_tf32(bf[j]);
            }
            #pragma unroll
            for (int i = 0; i < 2; i++)
                #pragma unroll
                for (int j = 0; j < 2; j++)
                    wmma::mma_sync(acc[i][j], a[i], bf[j], acc[i][j]);
        }
        #pragma unroll
        for (int i = 0; i < 2; i++)
            #pragma unroll
            for (int j = 0; j < 2; j++)
                wmma::store_matrix_sync(&Ss[(wr * 32 + i * 16) * 68 + wc * 32 + j * 16],
                                        acc[i][j], 68, wmma::mem_row_major);
        __syncthreads();

        // Scale + ALiBi, write biased scores to global + back to smem
        float* Abase = attn + ((size_t)bh * SEQ + i0) * SEQ + jt * 64;
        #pragma unroll
        for (int t = 0; t < 8; t++) {
            int idx = tid + t * 256;
            int r = idx >> 4, c = (idx & 15) * 4;
            float4 v = *(float4*)&Ss[r * 68 + c];
            const float base = slope * (float)(jt * 64 + c - (i0 + r));
            v.x = v.x * 0.125f + base;
            v.y = v.y * 0.125f + base + slope;
            v.z = v.z * 0.125f + base + 2.f * slope;
            v.w = v.w * 0.125f + base + 3.f * slope;
            *(float4*)&Ss[r * 68 + c] = v;
            *(float4*)&Abase[(size_t)r * SEQ + c] = v;
        }
        __syncthreads();

        // Online (max, sumexp) update: 2 threads per row
        {
            const int r = tid >> 1, half = tid & 1;
            const float* row = &Ss[r * 68 + half * 32];
            float mloc = row[0];
            #pragma unroll
            for (int k = 1; k < 32; k++) mloc = fmaxf(mloc, row[k]);
            float mt = fmaxf(mloc, __shfl_xor_sync(0xffffffffu, mloc, 1));
            float sl = 0.f;
            #pragma unroll
            for (int k = 0; k < 32; k++) sl += __expf(row[k] - mt);
            sl += __shfl_xor_sync(0xffffffffu, sl, 1);
            if (half == 0) {
                float mold = Ms[r];
                float mnew = fmaxf(mold, mt);
                Sums[r] = Sums[r] * __expf(mold - mnew) + sl * __expf(mt - mnew);
                Ms[r] = mnew;
            }
        }
    }
    __syncthreads();
    if (tid < 128) {
        stats[((size_t)bh * SEQ + i0 + tid) * 2 + 0] = Ms[tid];
        stats[((size_t)bh * SEQ + i0 + tid) * 2 + 1] = Sums[tid];
    }
}

// ---------------------------------------------------------------------------
// Kernel B: fused normalize + PV. Reads biased scores, writes softmax probs
// to attn, accumulates O = P @ V. Block = (i-tile 128, bh), 32 j-tiles of 64.
// ---------------------------------------------------------------------------
#define ASM_B ((128*68 + 2*64*68 + 256) * 4)   // 70656 B

__global__ __launch_bounds__(256) void pv_w(
    float* __restrict__ attn, const float* __restrict__ qkv,
    const float* __restrict__ stats, float* __restrict__ ctx)
{
    extern __shared__ float sm[];
    float* Ps = sm;                    // [128][68]
    float* Vs = sm + 128 * 68;         // 2 x [64][68]
    float* Ms = Vs + 2 * 64 * 68;      // [128]
    float* Is = Ms + 128;              // [128] 1/sum

    const int bh = blockIdx.y, b = bh >> 4, h = bh & 15;
    const int i0 = blockIdx.x * 128;
    float* Ag = attn + ((size_t)bh * SEQ + i0) * SEQ;
    const float* Vg = qkv + (size_t)b * SEQ * E3 + h * 192 + 128;
    const int tid = threadIdx.x;
    const int w = tid >> 5, wr = w >> 1, wc = w & 1;

    if (tid < 128) {
        float m = stats[((size_t)bh * SEQ + i0 + tid) * 2 + 0];
        float s = stats[((size_t)bh * SEQ + i0 + tid) * 2 + 1];
        Ms[tid] = m;
        Is[tid] = 1.f / s;
    }

    // Prefetch V tile 0
    #pragma unroll
    for (int t = 0; t < 4; t++) {
        int idx = tid + t * 256;
        int r = idx >> 4, c = (idx & 15) * 4;
        cpa16(&Vs[r * 68 + c], &Vg[(size_t)r * E3 + c]);
    }
    CP_COMMIT();

    FragC acc[2][2];
    #pragma unroll
    for (int i = 0; i < 2; i++)
        #pragma unroll
        for (int j = 0; j < 2; j++) wmma::fill_fragment(acc[i][j], 0.f);

    for (int jt = 0; jt < 32; jt++) {
        __syncthreads();
        if (jt + 1 < 32) {
            float* vb = Vs + ((jt + 1) & 1) * 64 * 68;
            const float* vg = Vg + (size_t)(jt + 1) * 64 * E3;
            #pragma unroll
            for (int t = 0; t < 4; t++) {
                int idx = tid + t * 256;
                int r = idx >> 4, c = (idx & 15) * 4;
                cpa16(&vb[r * 68 + c], &vg[(size_t)r * E3 + c]);
            }
            CP_COMMIT();
            CP_WAIT(1);
        } else {
            CP_WAIT(0);
        }
        __syncthreads();

        // Normalize: p = exp(v - m) / s ; write back to attn + stage to smem
        #pragma unroll
        for (int t = 0; t < 8; t++) {
            int idx = tid + t * 256;
            int r = idx >> 4, c = (idx & 15) * 4;
            float4 v = *(float4*)&Ag[(size_t)r * SEQ + jt * 64 + c];
            const float m = Ms[r], is = Is[r];
            v.x = __expf(v.x - m) * is;
            v.y = __expf(v.y - m) * is;
            v.z = __expf(v.z - m) * is;
            v.w = __expf(v.w - m) * is;
            *(float4*)&Ag[(size_t)r * SEQ + jt * 64 + c] = v;
            *(float4*)&Ps[r * 68 + c] = v;
        }
        __syncthreads();

        const float* vbuf = Vs + (jt & 1) * 64 * 68;
        #pragma unroll
        for (int kk = 0; kk < 64; kk += 8) {
            FragA a[2];
            FragBR bf[2];
            #pragma unroll
            for (int i = 0; i < 2; i++) {
                wmma::load_matrix_sync(a[i], &Ps[(wr * 32 + i * 16) * 68 + kk], 68);
                to_tf32(a[i]);
            }
            #pragma unroll
            for (int j = 0; j < 2; j++) {
                wmma::load_matrix_sync(bf[j], &vbuf[kk * 68 + wc * 32 + j * 16], 68);
                to_tf32(bf[j]);
            }
            #pragma unroll
            for (int i = 0; i < 2; i++)
                #pragma unroll
                for (int j = 0; j < 2; j++)
                    wmma::mma_sync(acc[i][j], a[i], bf[j], acc[i][j]);
        }
    }

    // Epilogue: O -> ctx
    #pragma unroll
    for (int i = 0; i < 2; i++) {
        const int q = i0 + wr * 32 + i * 16;
        #pragma unroll
        for (int j = 0; j < 2; j++)
            wmma::store_matrix_sync(
                &ctx[((size_t)(b * SEQ + q)) * EMB + h * HDIM + wc * 32 + j * 16],
                acc[i][j], EMB, wmma::mem_row_major);
    }
}

// ---------------------------------------------------------------------------
extern "C" void kernel_launch(void* const* d_in, const int* in_sizes, int n_in,
                              void* d_out, int out_size)
{
    const float* x    = (const float*)d_in[0];
    const float* Wqkv = (const float*)d_in[1];
    const float* bqkv = (const float*)d_in[2];
    const float* Wout = (const float*)d_in[3];
    const float* bout = (const float*)d_in[4];
    float* out = (float*)d_out;

    const long long OUT_ELEMS  = (long long)BATCH * SEQ * EMB;
    const long long ATTN_ELEMS = (long long)BATCH * NHEAD * SEQ * SEQ;

    float *qkv, *ctx, *stats, *attn;
    cudaGetSymbolAddress((void**)&qkv,   g_qkv);
    cudaGetSymbolAddress((void**)&ctx,   g_ctx);
    cudaGetSymbolAddress((void**)&stats, g_stats);
    if ((long long)out_size >= OUT_ELEMS + ATTN_ELEMS) {
        attn = out + OUT_ELEMS;
    } else {
        cudaGetSymbolAddress((void**)&attn, g_attn);
    }

    cudaFuncSetAttribute(gemm_bias_w,    cudaFuncAttributeMaxDynamicSharedMemorySize, GSM);
    cudaFuncSetAttribute(scores_stats_w, cudaFuncAttributeMaxDynamicSharedMemorySize, ASM_A);
    cudaFuncSetAttribute(pv_w,           cudaFuncAttributeMaxDynamicSharedMemorySize, ASM_B);

    const int M = BATCH * SEQ;  // 4096

    // 1) QKV projection
    gemm_bias_w<<<dim3(E3 / 128, M / 128), 256, GSM>>>(x, Wqkv, bqkv, qkv, EMB, E3);

    // 2) Scores + ALiBi + softmax stats (fused)
    scores_stats_w<<<dim3(SEQ / 128, BATCH * NHEAD), 256, ASM_A>>>(qkv, attn, stats);

    // 3) Normalize + PV (fused)
    pv_w<<<dim3(SEQ / 128, BATCH * NHEAD), 256, ASM_B>>>(attn, qkv, stats, ctx);

    // 4) Output projection
    gemm_bias_w<<<dim3(EMB / 128, M / 128), 256, GSM>>>(ctx, Wout, bout, out, EMB, EMB);
}

// round 6
// speedup vs baseline: 1.3942x; 1.3942x over previous
#include <cuda_runtime.h>
#include <mma.h>
#include <cstdint>
#include <math.h>

using namespace nvcuda;

#define BATCH 2
#define SEQ   2048
#define EMB   1024
#define NHEAD 16
#define HDIM  64
#define E3    3072

// Scratch (__device__ globals per allocation rules)
__device__ float g_qkv [(size_t)BATCH * SEQ * E3];            // 50 MB
__device__ float g_ctx [(size_t)BATCH * SEQ * EMB];           // 16 MB
__device__ float g_attn[(size_t)BATCH * NHEAD * SEQ * SEQ];   // 512 MB fallback

typedef wmma::fragment<wmma::matrix_a, 16, 16, 8, wmma::precision::tf32, wmma::row_major> FragA;
typedef wmma::fragment<wmma::matrix_b, 16, 16, 8, wmma::precision::tf32, wmma::row_major> FragBR;
typedef wmma::fragment<wmma::matrix_b, 16, 16, 8, wmma::precision::tf32, wmma::col_major> FragBC;
typedef wmma::fragment<wmma::accumulator, 16, 16, 8, float> FragC;

template<class F>
__device__ __forceinline__ void to_tf32(F& f) {
    #pragma unroll
    for (int i = 0; i < f.num_elements; i++) f.x[i] = wmma::__float_to_tf32(f.x[i]);
}

__device__ __forceinline__ void cpa16(float* s, const float* g) {
    uint32_t sa = (uint32_t)__cvta_generic_to_shared(s);
    asm volatile("cp.async.ca.shared.global [%0], [%1], 16;" :: "r"(sa), "l"(g));
}
#define CP_COMMIT() asm volatile("cp.async.commit_group;" ::: "memory")
#define CP_WAIT(n)  asm volatile("cp.async.wait_group %0;" :: "n"(n) : "memory")

// ---------------------------------------------------------------------------
// GEMM + bias: C[M,N] = A[M,K] @ B[K,N] + bias[N]
// BM=128, BN=128, BK=32, 256 threads, 2-stage cp.async pipeline.
// ---------------------------------------------------------------------------
#define AS_STRIDE 36
#define BS_STRIDE 132
#define AS_BUF (128 * AS_STRIDE)
#define BS_BUF (32 * BS_STRIDE)
#define GSM ((2 * AS_BUF + 2 * BS_BUF) * 4)   // 70656 B (Cs 67584 reuses prefix)

// A tile: 128 rows x 32 cols. 2 threads/row; each thread loads 16 floats
// = 4 cp.async at col offsets 0,4,8,12.
__device__ __forceinline__ void load_gemm_A(float* dst, const float* Ab,
                                            int lda, int tid) {
    const int ar = tid >> 1, ac = (tid & 1) * 16;
    const float* gp = Ab + (size_t)ar * lda + ac;
    float* sp = dst + ar * AS_STRIDE + ac;
    cpa16(sp + 0,  gp + 0);
    cpa16(sp + 4,  gp + 4);
    cpa16(sp + 8,  gp + 8);
    cpa16(sp + 12, gp + 12);
}
// B tile: 32 rows x 128 cols = 1024 float4, 4 per thread.
__device__ __forceinline__ void load_gemm_B(float* dst, const float* Bb,
                                            int ldb, int tid) {
    #pragma unroll
    for (int t = 0; t < 4; t++) {
        int idx = tid + t * 256;
        int r = idx >> 5, c = (idx & 31) * 4;
        cpa16(&dst[r * BS_STRIDE + c], &Bb[(size_t)r * ldb + c]);
    }
}

__global__ __launch_bounds__(256) void gemm_bias_w(
    const float* __restrict__ A, const float* __restrict__ B,
    const float* __restrict__ bias, float* __restrict__ C, int K, int N)
{
    extern __shared__ float sm[];
    float* As = sm;                    // 2 x [128][36]
    float* Bs = sm + 2 * AS_BUF;       // 2 x [32][132]
    float* Cs = sm;                    // [128][132] (reused after mainloop)

    const int m0 = blockIdx.y * 128, n0 = blockIdx.x * 128;
    const int tid = threadIdx.x;
    const int w = tid >> 5;
    const int wr = w >> 1, wc = w & 1;

    FragC acc[2][4];
    #pragma unroll
    for (int i = 0; i < 2; i++)
        #pragma unroll
        for (int j = 0; j < 4; j++) wmma::fill_fragment(acc[i][j], 0.f);

    const int nk = K / 32;

    // Prologue: prefetch chunk 0 into stage 0
    load_gemm_A(As, A + (size_t)m0 * K, K, tid);
    load_gemm_B(Bs, B + n0, N, tid);
    CP_COMMIT();

    for (int kt = 0; kt < nk; kt++) {
        const int cur = kt & 1;
        if (kt + 1 < nk) {
            const int k0 = (kt + 1) * 32;
            load_gemm_A(As + (cur ^ 1) * AS_BUF, A + (size_t)m0 * K + k0, K, tid);
            load_gemm_B(Bs + (cur ^ 1) * BS_BUF, B + (size_t)k0 * N + n0, N, tid);
            CP_COMMIT();
            CP_WAIT(1);
        } else {
            CP_WAIT(0);
        }
        __syncthreads();

        const float* Ac = As + cur * AS_BUF;
        const float* Bc = Bs + cur * BS_BUF;
        #pragma unroll
        for (int kk = 0; kk < 32; kk += 8) {
            FragA a[2];
            FragBR b[4];
            #pragma unroll
            for (int i = 0; i < 2; i++) {
                wmma::load_matrix_sync(a[i], &Ac[(wr * 32 + i * 16) * AS_STRIDE + kk], AS_STRIDE);
                to_tf32(a[i]);
            }
            #pragma unroll
            for (int j = 0; j < 4; j++) {
                wmma::load_matrix_sync(b[j], &Bc[kk * BS_STRIDE + wc * 64 + j * 16], BS_STRIDE);
                to_tf32(b[j]);
            }
            #pragma unroll
            for (int i = 0; i < 2; i++)
                #pragma unroll
                for (int j = 0; j < 4; j++)
                    wmma::mma_sync(acc[i][j], a[i], b[j], acc[i][j]);
        }
        __syncthreads();   // compute done before next prefetch overwrites this stage
    }

    // Epilogue via smem staging
    #pragma unroll
    for (int i = 0; i < 2; i++)
        #pragma unroll
        for (int j = 0; j < 4; j++)
            wmma::store_matrix_sync(&Cs[(wr * 32 + i * 16) * BS_STRIDE + wc * 64 + j * 16],
                                    acc[i][j], BS_STRIDE, wmma::mem_row_major);
    __syncthreads();
    #pragma unroll
    for (int t = 0; t < 16; t++) {
        int idx = tid + t * 256;
        int r = idx >> 5, c = (idx & 31) * 4;
        float4 v = *(float4*)&Cs[r * BS_STRIDE + c];
        const float* bp = bias + n0 + c;
        v.x += bp[0]; v.y += bp[1]; v.z += bp[2]; v.w += bp[3];
        *(float4*)&C[(size_t)(m0 + r) * N + n0 + c] = v;
    }
}

// ---------------------------------------------------------------------------
// Scores: attn[bh,i,j] = (Q_i . K_j)/8 + slope(h)*(j-i).  grid(16,16,32)
// Whole 128x64 Q and K tiles loaded once via cp.async; 8 mma k-steps.
// ---------------------------------------------------------------------------
#define QK_STRIDE 68
#define SSM (2 * 128 * QK_STRIDE * 4)   // 69632 B (Cs 67584 reuses prefix)

__global__ __launch_bounds__(256) void scores_w(
    const float* __restrict__ qkv, float* __restrict__ attn)
{
    extern __shared__ float sm[];
    float* Qs = sm;                      // [128][68]
    float* Ks = sm + 128 * QK_STRIDE;    // [128][68]
    float* Cs = sm;                      // [128][132] (reused)

    const int bh = blockIdx.z, b = bh >> 4, h = bh & 15;
    const int i0 = blockIdx.y * 128, j0 = blockIdx.x * 128;
    const float* Qg = qkv + (size_t)b * SEQ * E3 + h * 192;
    const float* Kg = qkv + (size_t)b * SEQ * E3 + h * 192 + 64;

    const int tid = threadIdx.x;
    const int w = tid >> 5;
    const int wr = w >> 1, wc = w & 1;

    // Load full tiles: 128 rows x 16 f4 each, for Q and K
    #pragma unroll
    for (int t = 0; t < 8; t++) {
        int idx = tid + t * 256;
        int r = idx >> 4, c = (idx & 15) * 4;
        cpa16(&Qs[r * QK_STRIDE + c], &Qg[(size_t)(i0 + r) * E3 + c]);
        cpa16(&Ks[r * QK_STRIDE + c], &Kg[(size_t)(j0 + r) * E3 + c]);
    }
    CP_COMMIT();
    CP_WAIT(0);
    __syncthreads();

    FragC acc[2][4];
    #pragma unroll
    for (int i = 0; i < 2; i++)
        #pragma unroll
        for (int j = 0; j < 4; j++) wmma::fill_fragment(acc[i][j], 0.f);

    #pragma unroll
    for (int kk = 0; kk < 64; kk += 8) {
        FragA a[2];
        FragBC bf[4];
        #pragma unroll
        for (int i = 0; i < 2; i++) {
            wmma::load_matrix_sync(a[i], &Qs[(wr * 32 + i * 16) * QK_STRIDE + kk], QK_STRIDE);
            to_tf32(a[i]);
        }
        #pragma unroll
        for (int j = 0; j < 4; j++) {
            wmma::load_matrix_sync(bf[j], &Ks[(wc * 64 + j * 16) * QK_STRIDE + kk], QK_STRIDE);
            to_tf32(bf[j]);
        }
        #pragma unroll
        for (int i = 0; i < 2; i++)
            #pragma unroll
            for (int j = 0; j < 4; j++)
                wmma::mma_sync(acc[i][j], a[i], bf[j], acc[i][j]);
    }
    __syncthreads();

    #pragma unroll
    for (int i = 0; i < 2; i++)
        #pragma unroll
        for (int j = 0; j < 4; j++)
            wmma::store_matrix_sync(&Cs[(wr * 32 + i * 16) * 132 + wc * 64 + j * 16],
                                    acc[i][j], 132, wmma::mem_row_major);
    __syncthreads();

    const float slope = exp2f(-0.5f * (float)(h + 1));
    #pragma unroll
    for (int t = 0; t < 16; t++) {
        int idx = tid + t * 256;
        int r = idx >> 5, c = (idx & 31) * 4;
        const int gi = i0 + r, gj = j0 + c;
        float4 v = *(float4*)&Cs[r * 132 + c];
        v.x = v.x * 0.125f + slope * (float)(gj + 0 - gi);
        v.y = v.y * 0.125f + slope * (float)(gj + 1 - gi);
        v.z = v.z * 0.125f + slope * (float)(gj + 2 - gi);
        v.w = v.w * 0.125f + slope * (float)(gj + 3 - gi);
        *(float4*)&attn[((size_t)bh * SEQ + gi) * SEQ + gj] = v;
    }
}

// ---------------------------------------------------------------------------
// AV: ctx[b,q,h*64+d] = sum_k attn[bh,q,k] * V[k,d].  grid(16, 32)
// BM=128, BN=64, BK=32; 2-stage cp.async pipeline over 64 k-chunks.
// ---------------------------------------------------------------------------
#define AVA_BUF (128 * 36)
#define AVV_BUF (32 * 68)
#define AVSM ((2 * AVA_BUF + 2 * AVV_BUF) * 4)   // 54272 B

// attn tile: 128 rows x 32 cols; 2 threads/row, 16 floats each = 4 cp.async.
__device__ __forceinline__ void load_av_A(float* dst, const float* Ab, int tid) {
    const int ar = tid >> 1, ac = (tid & 1) * 16;
    const float* gp = Ab + (size_t)ar * SEQ + ac;
    float* sp = dst + ar * 36 + ac;
    cpa16(sp + 0,  gp + 0);
    cpa16(sp + 4,  gp + 4);
    cpa16(sp + 8,  gp + 8);
    cpa16(sp + 12, gp + 12);
}
// V tile: 32 rows x 64 cols = 512 float4, 2 per thread.
__device__ __forceinline__ void load_av_V(float* dst, const float* Vb, int tid) {
    const int vr = tid >> 4, vc = (tid & 15) * 4;
    cpa16(&dst[vr * 68 + vc],        &Vb[(size_t)vr * E3 + vc]);
    cpa16(&dst[(vr + 16) * 68 + vc], &Vb[(size_t)(vr + 16) * E3 + vc]);
}

__global__ __launch_bounds__(256) void av_w(
    const float* __restrict__ attn, const float* __restrict__ qkv,
    float* __restrict__ ctx)
{
    extern __shared__ float sm[];
    float* As = sm;                    // 2 x [128][36]
    float* Vs = sm + 2 * AVA_BUF;      // 2 x [32][68]

    const int bh = blockIdx.y, b = bh >> 4, h = bh & 15;
    const int i0 = blockIdx.x * 128;
    const float* Ag = attn + ((size_t)bh * SEQ + i0) * SEQ;
    const float* Vg = qkv + (size_t)b * SEQ * E3 + h * 192 + 128;

    const int tid = threadIdx.x;
    const int w = tid >> 5;
    const int wr = w >> 1, wc = w & 1;

    FragC acc[2][2];
    #pragma unroll
    for (int i = 0; i < 2; i++)
        #pragma unroll
        for (int j = 0; j < 2; j++) wmma::fill_fragment(acc[i][j], 0.f);

    // Prologue: chunk 0 -> stage 0
    load_av_A(As, Ag, tid);
    load_av_V(Vs, Vg, tid);
    CP_COMMIT();

    const int nk = SEQ / 32;  // 64
    for (int kt = 0; kt < nk; kt++) {
        const int cur = kt & 1;
        if (kt + 1 < nk) {
            const int k0 = (kt + 1) * 32;
            load_av_A(As + (cur ^ 1) * AVA_BUF, Ag + k0, tid);
            load_av_V(Vs + (cur ^ 1) * AVV_BUF, Vg + (size_t)k0 * E3, tid);
            CP_COMMIT();
            CP_WAIT(1);
        } else {
            CP_WAIT(0);
        }
        __syncthreads();

        const float* Ac = As + cur * AVA_BUF;
        const float* Vc = Vs + cur * AVV_BUF;
        #pragma unroll
        for (int kk = 0; kk < 32; kk += 8) {
            FragA a[2];
            FragBR bf[2];
            #pragma unroll
            for (int i = 0; i < 2; i++) {
                wmma::load_matrix_sync(a[i], &Ac[(wr * 32 + i * 16) * 36 + kk], 36);
                to_tf32(a[i]);
            }
            #pragma unroll
            for (int j = 0; j < 2; j++) {
                wmma::load_matrix_sync(bf[j], &Vc[kk * 68 + wc * 32 + j * 16], 68);
                to_tf32(bf[j]);
            }
            #pragma unroll
            for (int i = 0; i < 2; i++)
                #pragma unroll
                for (int j = 0; j < 2; j++)
                    wmma::mma_sync(acc[i][j], a[i], bf[j], acc[i][j]);
        }
        __syncthreads();
    }

    #pragma unroll
    for (int i = 0; i < 2; i++) {
        const int q = i0 + wr * 32 + i * 16;
        #pragma unroll
        for (int j = 0; j < 2; j++)
            wmma::store_matrix_sync(
                &ctx[((size_t)(b * SEQ + q)) * EMB + h * HDIM + wc * 32 + j * 16],
                acc[i][j], EMB, wmma::mem_row_major);
    }
}

// ---------------------------------------------------------------------------
// Row softmax over last dim (S=2048), in place. One block (256 thr) per row.
// ---------------------------------------------------------------------------
__global__ __launch_bounds__(256) void softmax_kernel(float* __restrict__ attn)
{
    float* p = attn + (size_t)blockIdx.x * SEQ;
    const int tid = threadIdx.x;
    float4 a = ((const float4*)p)[tid];
    float4 b = ((const float4*)p)[tid + 256];

    float m = fmaxf(fmaxf(fmaxf(a.x, a.y), fmaxf(a.z, a.w)),
                    fmaxf(fmaxf(b.x, b.y), fmaxf(b.z, b.w)));
    #pragma unroll
    for (int o = 16; o > 0; o >>= 1)
        m = fmaxf(m, __shfl_xor_sync(0xffffffffu, m, o));

    __shared__ float sm_[8], ss[8];
    if ((tid & 31) == 0) sm_[tid >> 5] = m;
    __syncthreads();
    m = sm_[0];
    #pragma unroll
    for (int w = 1; w < 8; w++) m = fmaxf(m, sm_[w]);

    a.x = expf(a.x - m); a.y = expf(a.y - m); a.z = expf(a.z - m); a.w = expf(a.w - m);
    b.x = expf(b.x - m); b.y = expf(b.y - m); b.z = expf(b.z - m); b.w = expf(b.w - m);

    float s = a.x + a.y + a.z + a.w + b.x + b.y + b.z + b.w;
    #pragma unroll
    for (int o = 16; o > 0; o >>= 1)
        s += __shfl_xor_sync(0xffffffffu, s, o);
    if ((tid & 31) == 0) ss[tid >> 5] = s;
    __syncthreads();
    s = ss[0];
    #pragma unroll
    for (int w = 1; w < 8; w++) s += ss[w];

    const float inv = 1.0f / s;
    a.x *= inv; a.y *= inv; a.z *= inv; a.w *= inv;
    b.x *= inv; b.y *= inv; b.z *= inv; b.w *= inv;
    ((float4*)p)[tid]       = a;
    ((float4*)p)[tid + 256] = b;
}

// ---------------------------------------------------------------------------
extern "C" void kernel_launch(void* const* d_in, const int* in_sizes, int n_in,
                              void* d_out, int out_size)
{
    const float* x    = (const float*)d_in[0];
    const float* Wqkv = (const float*)d_in[1];
    const float* bqkv = (const float*)d_in[2];
    const float* Wout = (const float*)d_in[3];
    const float* bout = (const float*)d_in[4];
    float* out = (float*)d_out;

    const long long OUT_ELEMS  = (long long)BATCH * SEQ * EMB;
    const long long ATTN_ELEMS = (long long)BATCH * NHEAD * SEQ * SEQ;

    float *qkv, *ctx, *attn;
    cudaGetSymbolAddress((void**)&qkv, g_qkv);
    cudaGetSymbolAddress((void**)&ctx, g_ctx);
    if ((long long)out_size >= OUT_ELEMS + ATTN_ELEMS) {
        attn = out + OUT_ELEMS;
    } else {
        cudaGetSymbolAddress((void**)&attn, g_attn);
    }

    cudaFuncSetAttribute(gemm_bias_w, cudaFuncAttributeMaxDynamicSharedMemorySize, GSM);
    cudaFuncSetAttribute(scores_w,    cudaFuncAttributeMaxDynamicSharedMemorySize, SSM);
    cudaFuncSetAttribute(av_w,        cudaFuncAttributeMaxDynamicSharedMemorySize, AVSM);

    const int M = BATCH * SEQ;  // 4096

    // 1) QKV projection
    gemm_bias_w<<<dim3(E3 / 128, M / 128), 256, GSM>>>(x, Wqkv, bqkv, qkv, EMB, E3);

    // 2) Scores + ALiBi
    scores_w<<<dim3(SEQ / 128, SEQ / 128, BATCH * NHEAD), 256, SSM>>>(qkv, attn);

    // 3) Softmax
    softmax_kernel<<<BATCH * NHEAD * SEQ, 256>>>(attn);

    // 4) AV
    av_w<<<dim3(SEQ / 128, BATCH * NHEAD), 256, AVSM>>>(attn, qkv, ctx);

    // 5) Output projection
    gemm_bias_w<<<dim3(EMB / 128, M / 128), 256, GSM>>>(ctx, Wout, bout, out, EMB, EMB);
}